// round 11
// baseline (speedup 1.0000x reference)
#include <cuda_runtime.h>
#include <math.h>

#define SS 4096
#define VV 2048
#define BB 8
#define LL 32
#define WW 8
#define ZP 16

// Scratch (no allocation allowed in kernel_launch)
__device__ float g_lse[SS];
__device__ float g_prior[SS];
__device__ float g_logp[SS * 7];
__device__ float g_smt[(size_t)VV * SS];   // transposed smoothed emissions: [v][s]
__device__ float g_emis[LL * BB * SS];     // all_emis, layout (l, b, s)

// Order-preserving float <-> uint key (for REDUX.UMAX warp reduction)
__device__ __forceinline__ unsigned f2key(float f) {
    unsigned u = __float_as_uint(f);
    return u ^ (unsigned)(((int)u >> 31) | 0x80000000);
}
__device__ __forceinline__ float key2f(unsigned k) {
    unsigned u = (k & 0x80000000u) ? (k ^ 0x80000000u) : ~k;
    return __uint_as_float(u);
}

// ---------------------------------------------------------------------------
// K1: per-row logsumexp of emis_w (one warp per row, single global read)
// ---------------------------------------------------------------------------
__global__ void k_row_lse(const float* __restrict__ w) {
    int row  = blockIdx.x * 8 + (threadIdx.x >> 5);
    int lane = threadIdx.x & 31;
    const float4* r = (const float4*)(w + (size_t)row * VV);
    float4 v[16];
#pragma unroll
    for (int i = 0; i < 16; i++) v[i] = r[lane + 32 * i];
    float m = -1e30f;
#pragma unroll
    for (int i = 0; i < 16; i++)
        m = fmaxf(m, fmaxf(fmaxf(v[i].x, v[i].y), fmaxf(v[i].z, v[i].w)));
#pragma unroll
    for (int o = 16; o; o >>= 1) m = fmaxf(m, __shfl_xor_sync(0xffffffffu, m, o));
    float s = 0.f;
#pragma unroll
    for (int i = 0; i < 16; i++)
        s += __expf(v[i].x - m) + __expf(v[i].y - m)
           + __expf(v[i].z - m) + __expf(v[i].w - m);
#pragma unroll
    for (int o = 16; o; o >>= 1) s += __shfl_xor_sync(0xffffffffu, s, o);
    if (lane == 0) g_lse[row] = m + __logf(s);
}

// ---------------------------------------------------------------------------
// K1bc fused: block 0 = prior log_softmax; blocks 1..4 = transition logp
// ---------------------------------------------------------------------------
__global__ __launch_bounds__(1024) void k_small(const float* __restrict__ pw,
                                                const float* __restrict__ tw) {
    if (blockIdx.x == 0) {
        __shared__ float red[32];
        __shared__ float bval;
        int tid = threadIdx.x;
        float v[4];
#pragma unroll
        for (int i = 0; i < 4; i++) v[i] = pw[tid + i * 1024];
        float m = fmaxf(fmaxf(v[0], v[1]), fmaxf(v[2], v[3]));
#pragma unroll
        for (int o = 16; o; o >>= 1) m = fmaxf(m, __shfl_xor_sync(0xffffffffu, m, o));
        if ((tid & 31) == 0) red[tid >> 5] = m;
        __syncthreads();
        if (tid < 32) {
            float t = red[tid];
#pragma unroll
            for (int o = 16; o; o >>= 1) t = fmaxf(t, __shfl_xor_sync(0xffffffffu, t, o));
            if (tid == 0) bval = t;
        }
        __syncthreads();
        m = bval;
        float s = __expf(v[0] - m) + __expf(v[1] - m) + __expf(v[2] - m) + __expf(v[3] - m);
#pragma unroll
        for (int o = 16; o; o >>= 1) s += __shfl_xor_sync(0xffffffffu, s, o);
        if ((tid & 31) == 0) red[tid >> 5] = s;
        __syncthreads();
        if (tid < 32) {
            float t = red[tid];
#pragma unroll
            for (int o = 16; o; o >>= 1) t += __shfl_xor_sync(0xffffffffu, t, o);
            if (tid == 0) bval = t;
        }
        __syncthreads();
        float lse = m + __logf(bval);
#pragma unroll
        for (int i = 0; i < 4; i++) g_prior[tid + i * 1024] = v[i] - lse;
    } else {
        int j = (blockIdx.x - 1) * 1024 + threadIdx.x;
        int x = j & 15, y = (j >> 4) & 15, z = j >> 8;
        int v1 = (x < 15), v2 = (x > 0), v3 = (y < 15), v4 = (y > 0), v5 = (z < 15), v6 = (z < 14);
        int nv = 1 + v1 + v2 + v3 + v4 + v5 + v6;
        float w[7];
#pragma unroll
        for (int k = 0; k < 7; k++) w[k] = tw[j * 7 + k];
        float m = w[0];
#pragma unroll
        for (int k = 1; k < 7; k++) if (k < nv) m = fmaxf(m, w[k]);
        float s = 0.f;
#pragma unroll
        for (int k = 0; k < 7; k++) if (k < nv) s += __expf(w[k] - m);
        float lse = m + __logf(s);
        int p2 = 1 + v1;
        int p3 = p2 + v2;
        int p4 = p3 + v3;
        int p5 = p4 + v4;
        int p6 = p5 + v5;
        float* o = g_logp + j * 7;
        o[0] = w[0] - lse;
        o[1] = v1 ? w[1]  - lse : -1e30f;
        o[2] = v2 ? w[p2] - lse : -1e30f;
        o[3] = v3 ? w[p3] - lse : -1e30f;
        o[4] = v4 ? w[p4] - lse : -1e30f;
        o[5] = v5 ? w[p5] - lse : -1e30f;
        o[6] = v6 ? w[p6] - lse : -1e30f;
    }
}

// ---------------------------------------------------------------------------
// K2: smoothed emissions, stored TRANSPOSED (SMT[v][s]).
// One block = one z-plane (256 states) x 64 vocab columns, 512 threads.
// ---------------------------------------------------------------------------
__global__ __launch_bounds__(512) void k_smt(const float* __restrict__ ew) {
    extern __shared__ float P[];          // 256*67 floats = 68608 B
    __shared__ float slse[256];
    int tx = threadIdx.x & 31;
    int ty = threadIdx.x >> 5;            // 0..15
    int v0 = blockIdx.x * 64;
    int sbase = blockIdx.y * 256;         // z-plane

    if (threadIdx.x < 256) slse[threadIdx.x] = g_lse[sbase + threadIdx.x];
    __syncthreads();

#pragma unroll
    for (int i = 0; i < 16; i++) {
        int sl = ty + 16 * i;
        float l = slse[sl];
        const float* row = ew + (size_t)(sbase + sl) * VV + v0;
        P[sl * 67 + tx]      = __expf(row[tx]      - l);
        P[sl * 67 + 32 + tx] = __expf(row[32 + tx] - l);
    }
    __syncthreads();

#pragma unroll
    for (int jb = 0; jb < 8; jb++) {
        int sl = jb * 32 + tx;
        int x = sl & 15, y = sl >> 4;
        int sxp = sl + (x < 15);
        int sxm = sl - (x > 0);
        int syp = sl + ((y < 15) ? 16 : 0);
        int sym = sl - ((y > 0)  ? 16 : 0);
#pragma unroll
        for (int k = 0; k < 4; k++) {
            int vl = ty + 16 * k;          // 0..63
            float q = P[sl * 67 + vl] + P[sxp * 67 + vl] + P[sxm * 67 + vl]
                    + P[syp * 67 + vl] + P[sym * 67 + vl];
            g_smt[(size_t)(v0 + vl) * SS + sbase + sl] = __logf(q * 0.2f);
        }
    }
}

// ---------------------------------------------------------------------------
// K3: all_emis[l,b,s] = sum_w SMT[tok][s]  (tok == V contributes 0)
// Full-chip gather kernel (R8 lesson: do NOT fuse this into the 8-CTA k_fwd)
// ---------------------------------------------------------------------------
__global__ void k_emis(const int* __restrict__ stories) {
    int s  = blockIdx.x * 256 + threadIdx.x;
    int lb = blockIdx.y;           // lb = l*8 + b
    int l = lb >> 3, b = lb & 7;
    const int* tk = stories + (b * LL + l) * WW;
    float acc = 0.f;
#pragma unroll
    for (int w = 0; w < WW; w++) {
        int t = __ldg(&tk[w]);
        if (t < VV) acc += g_smt[(size_t)t * SS + s];
    }
    g_emis[(size_t)lb * SS + s] = acc;
}

// ---------------------------------------------------------------------------
// K4: forward recurrence, ONE barrier per step.
// Normalizer = per-WARP max (in-warp REDUX, no block reduction). Stored
// p~ = exp(sc - c_w) <= 1 (never overflows). Cross-warp gathers (y-edge,
// z+1 = +2 warps, z+2 = +4 warps) rescaled by exp(c_nb - c_w) from a
// 32-entry c-buffer. pbuf double-buffered -> no WAR barrier. Numerically
// safer than the reference (which uses one GLOBAL max in float32).
// ---------------------------------------------------------------------------
__global__ __launch_bounds__(1024, 1) void k_fwd(float* __restrict__ out) {
    __shared__ float pbuf[2][SS];
    __shared__ float cbuf[2][32];
    int b   = blockIdx.x;
    int tid = threadIdx.x;
    int wid = tid >> 5, lane = tid & 31;
    int j0 = tid * 4;
    int x0 = j0 & 15;          // 0,4,8,12
    int y  = (j0 >> 4) & 15;
    int z  = j0 >> 8;

    // warp indices for cross-warp scale lookups (clamped; invalid edges are
    // killed by Pk==0, clamp only prevents OOB)
    int wyp = min(wid + 1, 31);
    int wym = max(wid - 1, 0);
    int wzp = min(wid + 2, 31);
    int wzq = min(wid + 4, 31);
    bool edge_hi = (lane >= 28);   // y_local == 7 row
    bool edge_lo = (lane < 4);     // y_local == 0 row

    // Per-state amax + renormalized transition probs (once).
    float Pk[4][7], am[4];
#pragma unroll
    for (int e = 0; e < 4; e++) {
        const float* lp = g_logp + (j0 + e) * 7;
        float l[7];
#pragma unroll
        for (int k = 0; k < 7; k++) l[k] = lp[k];
        float m = l[0];
#pragma unroll
        for (int k = 1; k < 7; k++) m = fmaxf(m, l[k]);
        am[e] = m;
#pragma unroll
        for (int k = 0; k < 7; k++) Pk[e][k] = __expf(l[k] - m);  // invalid -> 0
    }

    // l = 0: score0 = emis[0,b,:] + prior
    float4 emv = *(const float4*)(g_emis + (size_t)b * SS + j0);
    float4 prv = *(const float4*)(g_prior + j0);
    float sc[4];
    sc[0] = emv.x + prv.x; sc[1] = emv.y + prv.y;
    sc[2] = emv.z + prv.z; sc[3] = emv.w + prv.w;
    *(float4*)(out + (size_t)b * SS + j0) = make_float4(sc[0], sc[1], sc[2], sc[3]);

    // per-warp max (no barrier)
    float lm = fmaxf(fmaxf(sc[0], sc[1]), fmaxf(sc[2], sc[3]));
    float cw = key2f(__reduce_max_sync(0xffffffffu, f2key(lm)));

    // prefetch emission for l = 1
    float4 emn = *(const float4*)(g_emis + (size_t)(BB + b) * SS + j0);

    int buf = 0;
    for (int l = 1; l < LL; l++) {
        // publish p~ = exp(sc - c_w) and c_w
        float4 p;
        p.x = __expf(sc[0] - cw); p.y = __expf(sc[1] - cw);
        p.z = __expf(sc[2] - cw); p.w = __expf(sc[3] - cw);
        *(float4*)(&pbuf[buf][j0]) = p;
        if (lane == 0) cbuf[buf][wid] = cw;

        // emission (+amax fold) for this step; prefetch next step's
        float emr[4] = {emn.x + am[0], emn.y + am[1], emn.z + am[2], emn.w + am[3]};
        if (l + 1 < LL)
            emn = *(const float4*)(g_emis + (size_t)((l + 1) * BB + b) * SS + j0);

        __syncthreads();   // the ONLY barrier per step

        // cross-warp rescale factors (y edges merged into one lane-selected exp)
        float ysel = edge_lo ? cbuf[buf][wym] : (edge_hi ? cbuf[buf][wyp] : cw);
        float s_y  = __expf(ysel - cw);                 // 1.0 for interior lanes
        float s_zp = __expf(cbuf[buf][wzp] - cw);
        float s_zq = __expf(cbuf[buf][wzq] - cw);

        const float* pb = pbuf[buf];
        float cm1 = (x0 > 0)  ? pb[j0 - 1] : p.x;
        float cp4 = (x0 < 12) ? pb[j0 + 4] : p.w;
        float4 yp = (y < 15) ? *(const float4*)(pb + j0 + 16)  : p;
        float4 ym = (y > 0)  ? *(const float4*)(pb + j0 - 16)  : p;
        float4 zp = (z < 15) ? *(const float4*)(pb + j0 + 256) : p;
        float4 zq = (z < 14) ? *(const float4*)(pb + j0 + 512) : p;

        // apply scales (edge-y rows get s_y; interiors s_y==1; invalid edges
        // produce finite junk that Pk==0 annihilates)
        float syp_f = edge_hi ? s_y : 1.f;
        float sym_f = edge_lo ? s_y : 1.f;
        yp.x *= syp_f; yp.y *= syp_f; yp.z *= syp_f; yp.w *= syp_f;
        ym.x *= sym_f; ym.y *= sym_f; ym.z *= sym_f; ym.w *= sym_f;
        zp.x *= s_zp;  zp.y *= s_zp;  zp.z *= s_zp;  zp.w *= s_zp;
        zq.x *= s_zq;  zq.y *= s_zq;  zq.z *= s_zq;  zq.w *= s_zq;

        float pc[4]  = {p.x, p.y, p.z, p.w};
        float pxp[4] = {p.y, p.z, p.w, cp4};
        float pxm[4] = {cm1, p.x, p.y, p.z};
        float pyp[4] = {yp.x, yp.y, yp.z, yp.w};
        float pym[4] = {ym.x, ym.y, ym.z, ym.w};
        float pzp[4] = {zp.x, zp.y, zp.z, zp.w};
        float pzq[4] = {zq.x, zq.y, zq.z, zq.w};

        float lmn = -1e30f;
#pragma unroll
        for (int e = 0; e < 4; e++) {
            float q = pc[e]  * Pk[e][0];
            q = fmaf(pxp[e], Pk[e][1], q);
            q = fmaf(pxm[e], Pk[e][2], q);
            q = fmaf(pyp[e], Pk[e][3], q);
            q = fmaf(pym[e], Pk[e][4], q);
            q = fmaf(pzp[e], Pk[e][5], q);
            q = fmaf(pzq[e], Pk[e][6], q);
            sc[e] = emr[e] + __logf(q) + cw;
            lmn = fmaxf(lmn, sc[e]);
        }
        *(float4*)(out + (size_t)(l * BB + b) * SS + j0) =
            make_float4(sc[0], sc[1], sc[2], sc[3]);

        // next step's per-warp normalizer (in-warp, no barrier)
        cw = key2f(__reduce_max_sync(0xffffffffu, f2key(lmn)));
        buf ^= 1;
    }
}

// ---------------------------------------------------------------------------
extern "C" void kernel_launch(void* const* d_in, const int* in_sizes, int n_in,
                              void* d_out, int out_size) {
    const int*   stories = nullptr;
    const float* trans_w = nullptr;
    const float* emis_w  = nullptr;
    const float* prior_w = nullptr;
    for (int i = 0; i < n_in; i++) {
        switch (in_sizes[i]) {
            case 2048:            stories = (const int*)d_in[i];   break;
            case 28672:           trans_w = (const float*)d_in[i]; break;
            case SS * VV:         emis_w  = (const float*)d_in[i]; break;
            case SS:              prior_w = (const float*)d_in[i]; break;
            default: break;
        }
    }
    float* out = (float*)d_out;

    const int smt_smem = 256 * 67 * sizeof(float);   // 68608 B
    cudaFuncSetAttribute(k_smt, cudaFuncAttributeMaxDynamicSharedMemorySize, smt_smem);

    k_row_lse<<<512, 256>>>(emis_w);
    k_small<<<5, 1024>>>(prior_w, trans_w);
    k_smt<<<dim3(VV / 64, ZP), 512, smt_smem>>>(emis_w);
    k_emis<<<dim3(SS / 256, LL * BB), 256>>>(stories);
    k_fwd<<<BB, 1024>>>(out);
    (void)out_size;
}

// round 13
// speedup vs baseline: 1.1020x; 1.1020x over previous
#include <cuda_runtime.h>
#include <math.h>

#define SS 4096
#define VV 2048
#define BB 8
#define LL 32
#define WW 8
#define ZP 16
#define HS 2048   // states per CTA in the 2-CTA-cluster forward kernel

// Scratch (no allocation allowed in kernel_launch)
__device__ float g_lse[SS];
__device__ float g_prior[SS];
__device__ float g_logp[SS * 7];
__device__ float g_smt[(size_t)VV * SS];   // transposed smoothed emissions: [v][s]
__device__ float g_emis[LL * BB * SS];     // all_emis, layout (l, b, s)

// Order-preserving float <-> uint key (for REDUX.UMAX warp reduction)
__device__ __forceinline__ unsigned f2key(float f) {
    unsigned u = __float_as_uint(f);
    return u ^ (unsigned)(((int)u >> 31) | 0x80000000);
}
__device__ __forceinline__ float key2f(unsigned k) {
    unsigned u = (k & 0x80000000u) ? (k ^ 0x80000000u) : ~k;
    return __uint_as_float(u);
}

__device__ __forceinline__ unsigned smem_u32(const void* p) {
    return (unsigned)__cvta_generic_to_shared(p);
}
__device__ __forceinline__ unsigned mapa_peer(unsigned laddr, unsigned rank) {
    unsigned r;
    asm("mapa.shared::cluster.u32 %0, %1, %2;" : "=r"(r) : "r"(laddr), "r"(rank));
    return r;
}
__device__ __forceinline__ float4 dsmem_ld4(unsigned addr) {
    float4 v;
    asm volatile("ld.shared::cluster.v4.f32 {%0,%1,%2,%3}, [%4];"
                 : "=f"(v.x), "=f"(v.y), "=f"(v.z), "=f"(v.w) : "r"(addr));
    return v;
}
__device__ __forceinline__ float dsmem_ldf(unsigned addr) {
    float v;
    asm volatile("ld.shared::cluster.f32 %0, [%1];" : "=f"(v) : "r"(addr));
    return v;
}

// ---------------------------------------------------------------------------
// K_pre fused (512 threads/block):
//   block 0        : prior log_softmax (8 elems/thread)
//   blocks 1..8    : transition logp (512 states/block)
//   blocks 9..264  : row-lse of emis_w (16 warps -> 16 rows/block, 256 blocks)
// ---------------------------------------------------------------------------
__global__ __launch_bounds__(512) void k_pre(const float* __restrict__ pw,
                                             const float* __restrict__ tw,
                                             const float* __restrict__ ew) {
    int bid = blockIdx.x;
    if (bid == 0) {
        __shared__ float red[16];
        __shared__ float bval;
        int tid = threadIdx.x;
        float v[8];
#pragma unroll
        for (int i = 0; i < 8; i++) v[i] = pw[tid + i * 512];
        float m = v[0];
#pragma unroll
        for (int i = 1; i < 8; i++) m = fmaxf(m, v[i]);
#pragma unroll
        for (int o = 16; o; o >>= 1) m = fmaxf(m, __shfl_xor_sync(0xffffffffu, m, o));
        if ((tid & 31) == 0) red[tid >> 5] = m;
        __syncthreads();
        if (tid < 16) {
            float t = red[tid];
#pragma unroll
            for (int o = 8; o; o >>= 1) t = fmaxf(t, __shfl_xor_sync(0xffffu, t, o));
            if (tid == 0) bval = t;
        }
        __syncthreads();
        m = bval;
        float s = 0.f;
#pragma unroll
        for (int i = 0; i < 8; i++) s += __expf(v[i] - m);
#pragma unroll
        for (int o = 16; o; o >>= 1) s += __shfl_xor_sync(0xffffffffu, s, o);
        if ((tid & 31) == 0) red[tid >> 5] = s;
        __syncthreads();
        if (tid < 16) {
            float t = red[tid];
#pragma unroll
            for (int o = 8; o; o >>= 1) t += __shfl_xor_sync(0xffffu, t, o);
            if (tid == 0) bval = t;
        }
        __syncthreads();
        float lse = m + __logf(bval);
#pragma unroll
        for (int i = 0; i < 8; i++) g_prior[tid + i * 512] = v[i] - lse;
    } else if (bid <= 8) {
        int j = (bid - 1) * 512 + threadIdx.x;
        int x = j & 15, y = (j >> 4) & 15, z = j >> 8;
        int v1 = (x < 15), v2 = (x > 0), v3 = (y < 15), v4 = (y > 0), v5 = (z < 15), v6 = (z < 14);
        int nv = 1 + v1 + v2 + v3 + v4 + v5 + v6;
        float w[7];
#pragma unroll
        for (int k = 0; k < 7; k++) w[k] = tw[j * 7 + k];
        float m = w[0];
#pragma unroll
        for (int k = 1; k < 7; k++) if (k < nv) m = fmaxf(m, w[k]);
        float s = 0.f;
#pragma unroll
        for (int k = 0; k < 7; k++) if (k < nv) s += __expf(w[k] - m);
        float lse = m + __logf(s);
        int p2 = 1 + v1;
        int p3 = p2 + v2;
        int p4 = p3 + v3;
        int p5 = p4 + v4;
        int p6 = p5 + v5;
        float* o = g_logp + j * 7;
        o[0] = w[0] - lse;
        o[1] = v1 ? w[1]  - lse : -1e30f;
        o[2] = v2 ? w[p2] - lse : -1e30f;
        o[3] = v3 ? w[p3] - lse : -1e30f;
        o[4] = v4 ? w[p4] - lse : -1e30f;
        o[5] = v5 ? w[p5] - lse : -1e30f;
        o[6] = v6 ? w[p6] - lse : -1e30f;
    } else {
        int row  = (bid - 9) * 16 + (threadIdx.x >> 5);
        int lane = threadIdx.x & 31;
        const float4* r = (const float4*)(ew + (size_t)row * VV);
        float4 v[16];
#pragma unroll
        for (int i = 0; i < 16; i++) v[i] = r[lane + 32 * i];
        float m = -1e30f;
#pragma unroll
        for (int i = 0; i < 16; i++)
            m = fmaxf(m, fmaxf(fmaxf(v[i].x, v[i].y), fmaxf(v[i].z, v[i].w)));
#pragma unroll
        for (int o = 16; o; o >>= 1) m = fmaxf(m, __shfl_xor_sync(0xffffffffu, m, o));
        float s = 0.f;
#pragma unroll
        for (int i = 0; i < 16; i++)
            s += __expf(v[i].x - m) + __expf(v[i].y - m)
               + __expf(v[i].z - m) + __expf(v[i].w - m);
#pragma unroll
        for (int o = 16; o; o >>= 1) s += __shfl_xor_sync(0xffffffffu, s, o);
        if (lane == 0) g_lse[row] = m + __logf(s);
    }
}

// ---------------------------------------------------------------------------
// K2: smoothed emissions, stored TRANSPOSED (SMT[v][s]). (unchanged, proven)
// ---------------------------------------------------------------------------
__global__ __launch_bounds__(512) void k_smt(const float* __restrict__ ew) {
    extern __shared__ float P[];          // 256*67 floats = 68608 B
    __shared__ float slse[256];
    int tx = threadIdx.x & 31;
    int ty = threadIdx.x >> 5;            // 0..15
    int v0 = blockIdx.x * 64;
    int sbase = blockIdx.y * 256;         // z-plane

    if (threadIdx.x < 256) slse[threadIdx.x] = g_lse[sbase + threadIdx.x];
    __syncthreads();

#pragma unroll
    for (int i = 0; i < 16; i++) {
        int sl = ty + 16 * i;
        float l = slse[sl];
        const float* row = ew + (size_t)(sbase + sl) * VV + v0;
        P[sl * 67 + tx]      = __expf(row[tx]      - l);
        P[sl * 67 + 32 + tx] = __expf(row[32 + tx] - l);
    }
    __syncthreads();

#pragma unroll
    for (int jb = 0; jb < 8; jb++) {
        int sl = jb * 32 + tx;
        int x = sl & 15, y = sl >> 4;
        int sxp = sl + (x < 15);
        int sxm = sl - (x > 0);
        int syp = sl + ((y < 15) ? 16 : 0);
        int sym = sl - ((y > 0)  ? 16 : 0);
#pragma unroll
        for (int k = 0; k < 4; k++) {
            int vl = ty + 16 * k;          // 0..63
            float q = P[sl * 67 + vl] + P[sxp * 67 + vl] + P[sxm * 67 + vl]
                    + P[syp * 67 + vl] + P[sym * 67 + vl];
            g_smt[(size_t)(v0 + vl) * SS + sbase + sl] = __logf(q * 0.2f);
        }
    }
}

// ---------------------------------------------------------------------------
// K3: all_emis, float4-vectorized (4 states/thread, 8 float4 loads in flight)
// ---------------------------------------------------------------------------
__global__ void k_emis(const int* __restrict__ stories) {
    __shared__ int tk[WW];
    int s4 = blockIdx.x * 256 + threadIdx.x;   // float4 index (0..1023)
    int lb = blockIdx.y;                       // lb = l*8 + b
    int l = lb >> 3, b = lb & 7;
    if (threadIdx.x < WW) tk[threadIdx.x] = stories[(b * LL + l) * WW + threadIdx.x];
    __syncthreads();
    float4 acc = make_float4(0.f, 0.f, 0.f, 0.f);
#pragma unroll
    for (int w = 0; w < WW; w++) {
        int t = tk[w];
        if (t < VV) {
            float4 v = ((const float4*)(g_smt + (size_t)t * SS))[s4];
            acc.x += v.x; acc.y += v.y; acc.z += v.z; acc.w += v.w;
        }
    }
    ((float4*)g_emis)[(size_t)lb * (SS / 4) + s4] = acc;
}

// ---------------------------------------------------------------------------
// K4: forward recurrence on 2-CTA clusters (one cluster per batch, 16 SMs).
// rank0 owns z=0..7, rank1 owns z=8..15. z-offsets are +1/+2 only, so data
// flows one direction: rank0 reads rank1's planes 8,9 (and the matching
// per-warp normalizers) via DSMEM. Per-step handshake: publish -> syncthreads
// -> fence + arrive on PEER's mbarrier -> wait OWN mbarrier (parity) -> fence.
// Double buffering + the symmetric handshake bounds skew to 1 step (WAR-safe).
// ---------------------------------------------------------------------------
__global__ __launch_bounds__(512, 1) __cluster_dims__(2, 1, 1)
void k_fwd(float* __restrict__ out) {
    __shared__ float pbuf[2][HS];
    __shared__ float cbuf[2][16];
    __shared__ __align__(8) unsigned long long mbar;

    int tid = threadIdx.x;
    int wid = tid >> 5, lane = tid & 31;
    unsigned rank;
    asm("mov.u32 %0, %%cluster_ctarank;" : "=r"(rank));
    unsigned peer = rank ^ 1u;
    int b   = blockIdx.x >> 1;
    int j0l = tid * 4;                 // local state (0..2044)
    int jg  = (int)rank * HS + j0l;    // global state
    int x0 = jg & 15;
    int y  = (jg >> 4) & 15;

    // mbarrier init + cluster-wide visibility
    if (tid == 0) {
        unsigned a = smem_u32(&mbar);
        asm volatile("mbarrier.init.shared.b64 [%0], 1;" :: "r"(a) : "memory");
    }
    asm volatile("barrier.cluster.arrive.aligned;" ::: "memory");
    asm volatile("barrier.cluster.wait.aligned;" ::: "memory");

    // local + peer addresses
    unsigned pb_l[2] = { smem_u32(&pbuf[0][0]), smem_u32(&pbuf[1][0]) };
    unsigned cb_l[2] = { smem_u32(&cbuf[0][0]), smem_u32(&cbuf[1][0]) };
    unsigned mb_l    = smem_u32(&mbar);
    unsigned pb_r[2], cb_r[2], mb_r;
    pb_r[0] = mapa_peer(pb_l[0], peer);
    pb_r[1] = mapa_peer(pb_l[1], peer);
    cb_r[0] = mapa_peer(cb_l[0], peer);
    cb_r[1] = mapa_peer(cb_l[1], peer);
    mb_r    = mapa_peer(mb_l, peer);

    // Per-state amax + renormalized transition probs (once).
    float Pk[4][7], am[4];
#pragma unroll
    for (int e = 0; e < 4; e++) {
        const float* lp = g_logp + (jg + e) * 7;
        float l[7];
#pragma unroll
        for (int k = 0; k < 7; k++) l[k] = lp[k];
        float m = l[0];
#pragma unroll
        for (int k = 1; k < 7; k++) m = fmaxf(m, l[k]);
        am[e] = m;
#pragma unroll
        for (int k = 0; k < 7; k++) Pk[e][k] = __expf(l[k] - m);  // invalid -> 0
    }

    // warp indices for scale lookups (y never crosses the CTA; z may)
    int wyp = min(wid + 1, 15);
    int wym = max(wid - 1, 0);
    bool edge_hi = (lane >= 28);   // top y-row of this warp's half-plane
    bool edge_lo = (lane < 4);     // bottom y-row

    // l = 0: score0 = emis[0,b,:] + prior
    float4 emv = *(const float4*)(g_emis + (size_t)b * SS + jg);
    float4 prv = *(const float4*)(g_prior + jg);
    float sc[4];
    sc[0] = emv.x + prv.x; sc[1] = emv.y + prv.y;
    sc[2] = emv.z + prv.z; sc[3] = emv.w + prv.w;
    *(float4*)(out + (size_t)b * SS + jg) = make_float4(sc[0], sc[1], sc[2], sc[3]);

    float lm = fmaxf(fmaxf(sc[0], sc[1]), fmaxf(sc[2], sc[3]));
    float cw = key2f(__reduce_max_sync(0xffffffffu, f2key(lm)));

    // prefetch emission for l = 1
    float4 emn = *(const float4*)(g_emis + (size_t)(BB + b) * SS + jg);

    int buf = 0;
    unsigned ph = 0;
    for (int l = 1; l < LL; l++) {
        // publish p~ = exp(sc - c_w) and c_w
        float4 p;
        p.x = __expf(sc[0] - cw); p.y = __expf(sc[1] - cw);
        p.z = __expf(sc[2] - cw); p.w = __expf(sc[3] - cw);
        *(float4*)(&pbuf[buf][j0l]) = p;
        if (lane == 0) cbuf[buf][wid] = cw;

        float emr[4] = {emn.x + am[0], emn.y + am[1], emn.z + am[2], emn.w + am[3]};
        if (l + 1 < LL)
            emn = *(const float4*)(g_emis + (size_t)((l + 1) * BB + b) * SS + jg);

        __syncthreads();                       // own pbuf/cbuf complete
        if (tid == 0) {
            asm volatile("fence.acq_rel.cluster;" ::: "memory");
            asm volatile("mbarrier.arrive.shared::cluster.b64 _, [%0];"
                         :: "r"(mb_r) : "memory");
        }
        // wait for peer's publication (and backpressure)
        {
            unsigned done = 0;
            while (!done) {
                asm volatile(
                    "{\n\t.reg .pred p;\n\t"
                    "mbarrier.try_wait.parity.acquire.cta.shared::cta.b64 p, [%1], %2;\n\t"
                    "selp.b32 %0, 1, 0, p;\n\t}"
                    : "=r"(done) : "r"(mb_l), "r"(ph) : "memory");
            }
        }
        asm volatile("fence.acq_rel.cluster;" ::: "memory");
        ph ^= 1u;

        // cross-warp rescale factors
        float ysel = edge_lo ? cbuf[buf][wym] : (edge_hi ? cbuf[buf][wyp] : cw);
        float s_y  = __expf(ysel - cw);
        float czp, czq;
        int wzp = wid + 2, wzq = wid + 4;
        if (wzp < 16)        czp = cbuf[buf][wzp];
        else if (rank == 0)  czp = dsmem_ldf(cb_r[buf] + (unsigned)(wzp - 16) * 4u);
        else                 czp = cw;   // global z >= 16: Pk==0 kills it
        if (wzq < 16)        czq = cbuf[buf][wzq];
        else if (rank == 0)  czq = dsmem_ldf(cb_r[buf] + (unsigned)(wzq - 16) * 4u);
        else                 czq = cw;
        float s_zp = __expf(czp - cw);
        float s_zq = __expf(czq - cw);

        const float* pb = pbuf[buf];
        float cm1 = (x0 > 0)  ? pb[j0l - 1] : p.x;
        float cp4 = (x0 < 12) ? pb[j0l + 4] : p.w;
        float4 yp = (y < 15) ? *(const float4*)(pb + j0l + 16) : p;
        float4 ym = (y > 0)  ? *(const float4*)(pb + j0l - 16) : p;

        int izp = j0l + 256, izq = j0l + 512;
        float4 zp, zq;
        if (izp < HS)        zp = *(const float4*)(pb + izp);
        else if (rank == 0)  zp = dsmem_ld4(pb_r[buf] + (unsigned)(izp - HS) * 4u);
        else                 zp = p;     // global z+1 >= 16: Pk==0
        if (izq < HS)        zq = *(const float4*)(pb + izq);
        else if (rank == 0)  zq = dsmem_ld4(pb_r[buf] + (unsigned)(izq - HS) * 4u);
        else                 zq = p;     // global z+2 >= 16: Pk==0

        float syp_f = edge_hi ? s_y : 1.f;
        float sym_f = edge_lo ? s_y : 1.f;
        yp.x *= syp_f; yp.y *= syp_f; yp.z *= syp_f; yp.w *= syp_f;
        ym.x *= sym_f; ym.y *= sym_f; ym.z *= sym_f; ym.w *= sym_f;
        zp.x *= s_zp;  zp.y *= s_zp;  zp.z *= s_zp;  zp.w *= s_zp;
        zq.x *= s_zq;  zq.y *= s_zq;  zq.z *= s_zq;  zq.w *= s_zq;

        float pc[4]  = {p.x, p.y, p.z, p.w};
        float pxp[4] = {p.y, p.z, p.w, cp4};
        float pxm[4] = {cm1, p.x, p.y, p.z};
        float pyp[4] = {yp.x, yp.y, yp.z, yp.w};
        float pym[4] = {ym.x, ym.y, ym.z, ym.w};
        float pzp[4] = {zp.x, zp.y, zp.z, zp.w};
        float pzq[4] = {zq.x, zq.y, zq.z, zq.w};

        float lmn = -1e30f;
#pragma unroll
        for (int e = 0; e < 4; e++) {
            float q = pc[e]  * Pk[e][0];
            q = fmaf(pxp[e], Pk[e][1], q);
            q = fmaf(pxm[e], Pk[e][2], q);
            q = fmaf(pyp[e], Pk[e][3], q);
            q = fmaf(pym[e], Pk[e][4], q);
            q = fmaf(pzp[e], Pk[e][5], q);
            q = fmaf(pzq[e], Pk[e][6], q);
            sc[e] = emr[e] + __logf(q) + cw;
            lmn = fmaxf(lmn, sc[e]);
        }
        *(float4*)(out + (size_t)(l * BB + b) * SS + jg) =
            make_float4(sc[0], sc[1], sc[2], sc[3]);

        cw = key2f(__reduce_max_sync(0xffffffffu, f2key(lmn)));
        buf ^= 1;
    }

    // keep SMEM alive until the peer is done with its remote reads/arrives
    asm volatile("barrier.cluster.arrive.aligned;" ::: "memory");
    asm volatile("barrier.cluster.wait.aligned;" ::: "memory");
}

// ---------------------------------------------------------------------------
extern "C" void kernel_launch(void* const* d_in, const int* in_sizes, int n_in,
                              void* d_out, int out_size) {
    const int*   stories = nullptr;
    const float* trans_w = nullptr;
    const float* emis_w  = nullptr;
    const float* prior_w = nullptr;
    for (int i = 0; i < n_in; i++) {
        switch (in_sizes[i]) {
            case 2048:            stories = (const int*)d_in[i];   break;
            case 28672:           trans_w = (const float*)d_in[i]; break;
            case SS * VV:         emis_w  = (const float*)d_in[i]; break;
            case SS:              prior_w = (const float*)d_in[i]; break;
            default: break;
        }
    }
    float* out = (float*)d_out;

    const int smt_smem = 256 * 67 * sizeof(float);   // 68608 B
    cudaFuncSetAttribute(k_smt, cudaFuncAttributeMaxDynamicSharedMemorySize, smt_smem);

    k_pre<<<265, 512>>>(prior_w, trans_w, emis_w);
    k_smt<<<dim3(VV / 64, ZP), 512, smt_smem>>>(emis_w);
    k_emis<<<dim3(SS / 1024, LL * BB), 256>>>(stories);
    k_fwd<<<BB * 2, 512>>>(out);
    (void)out_size;
}

// round 15
// speedup vs baseline: 1.1930x; 1.0825x over previous
#include <cuda_runtime.h>
#include <math.h>

#define SS 4096
#define VV 2048
#define BB 8
#define LL 32
#define WW 8
#define ZP 16
#define HS 2048      // states per CTA in the 2-CTA-cluster forward kernel
#define HSTRIDE 520  // halo slot stride (512 plane floats + 8 c-slots)

// Scratch (no allocation allowed in kernel_launch)
__device__ float g_lse[SS];
__device__ float g_prior[SS];
__device__ float g_logp[SS * 7];
__device__ float g_smt[(size_t)VV * SS];   // transposed smoothed emissions: [v][s]
__device__ float g_emis[LL * BB * SS];     // all_emis, layout (l, b, s)

// Order-preserving float <-> uint key (for REDUX.UMAX warp reduction)
__device__ __forceinline__ unsigned f2key(float f) {
    unsigned u = __float_as_uint(f);
    return u ^ (unsigned)(((int)u >> 31) | 0x80000000);
}
__device__ __forceinline__ float key2f(unsigned k) {
    unsigned u = (k & 0x80000000u) ? (k ^ 0x80000000u) : ~k;
    return __uint_as_float(u);
}

__device__ __forceinline__ unsigned smem_u32(const void* p) {
    return (unsigned)__cvta_generic_to_shared(p);
}
__device__ __forceinline__ unsigned mapa_peer(unsigned laddr, unsigned rank) {
    unsigned r;
    asm("mapa.shared::cluster.u32 %0, %1, %2;" : "=r"(r) : "r"(laddr), "r"(rank));
    return r;
}
__device__ __forceinline__ void dsmem_st4(unsigned addr, float4 v) {
    asm volatile("st.shared::cluster.v4.f32 [%0], {%1,%2,%3,%4};"
                 :: "r"(addr), "f"(v.x), "f"(v.y), "f"(v.z), "f"(v.w) : "memory");
}
__device__ __forceinline__ void dsmem_stf(unsigned addr, float v) {
    asm volatile("st.shared::cluster.f32 [%0], %1;" :: "r"(addr), "f"(v) : "memory");
}
__device__ __forceinline__ void dsmem_stu(unsigned addr, unsigned v) {
    asm volatile("st.shared::cluster.u32 [%0], %1;" :: "r"(addr), "r"(v) : "memory");
}
// Poll a monotonically increasing local-smem counter until >= target.
__device__ __forceinline__ void seq_wait(unsigned addr, unsigned target) {
    unsigned v;
    do {
        asm volatile("ld.volatile.shared.u32 %0, [%1];" : "=r"(v) : "r"(addr));
    } while (v < target);
}

// ---------------------------------------------------------------------------
// K_pre fused (512 threads/block):
//   block 0        : prior log_softmax (8 elems/thread)
//   blocks 1..8    : transition logp (512 states/block)
//   blocks 9..264  : row-lse of emis_w (16 warps -> 16 rows/block, 256 blocks)
// ---------------------------------------------------------------------------
__global__ __launch_bounds__(512) void k_pre(const float* __restrict__ pw,
                                             const float* __restrict__ tw,
                                             const float* __restrict__ ew) {
    int bid = blockIdx.x;
    if (bid == 0) {
        __shared__ float red[16];
        __shared__ float bval;
        int tid = threadIdx.x;
        float v[8];
#pragma unroll
        for (int i = 0; i < 8; i++) v[i] = pw[tid + i * 512];
        float m = v[0];
#pragma unroll
        for (int i = 1; i < 8; i++) m = fmaxf(m, v[i]);
#pragma unroll
        for (int o = 16; o; o >>= 1) m = fmaxf(m, __shfl_xor_sync(0xffffffffu, m, o));
        if ((tid & 31) == 0) red[tid >> 5] = m;
        __syncthreads();
        if (tid < 16) {
            float t = red[tid];
#pragma unroll
            for (int o = 8; o; o >>= 1) t = fmaxf(t, __shfl_xor_sync(0xffffu, t, o));
            if (tid == 0) bval = t;
        }
        __syncthreads();
        m = bval;
        float s = 0.f;
#pragma unroll
        for (int i = 0; i < 8; i++) s += __expf(v[i] - m);
#pragma unroll
        for (int o = 16; o; o >>= 1) s += __shfl_xor_sync(0xffffffffu, s, o);
        if ((tid & 31) == 0) red[tid >> 5] = s;
        __syncthreads();
        if (tid < 16) {
            float t = red[tid];
#pragma unroll
            for (int o = 8; o; o >>= 1) t += __shfl_xor_sync(0xffffu, t, o);
            if (tid == 0) bval = t;
        }
        __syncthreads();
        float lse = m + __logf(bval);
#pragma unroll
        for (int i = 0; i < 8; i++) g_prior[tid + i * 512] = v[i] - lse;
    } else if (bid <= 8) {
        int j = (bid - 1) * 512 + threadIdx.x;
        int x = j & 15, y = (j >> 4) & 15, z = j >> 8;
        int v1 = (x < 15), v2 = (x > 0), v3 = (y < 15), v4 = (y > 0), v5 = (z < 15), v6 = (z < 14);
        int nv = 1 + v1 + v2 + v3 + v4 + v5 + v6;
        float w[7];
#pragma unroll
        for (int k = 0; k < 7; k++) w[k] = tw[j * 7 + k];
        float m = w[0];
#pragma unroll
        for (int k = 1; k < 7; k++) if (k < nv) m = fmaxf(m, w[k]);
        float s = 0.f;
#pragma unroll
        for (int k = 0; k < 7; k++) if (k < nv) s += __expf(w[k] - m);
        float lse = m + __logf(s);
        int p2 = 1 + v1;
        int p3 = p2 + v2;
        int p4 = p3 + v3;
        int p5 = p4 + v4;
        int p6 = p5 + v5;
        float* o = g_logp + j * 7;
        o[0] = w[0] - lse;
        o[1] = v1 ? w[1]  - lse : -1e30f;
        o[2] = v2 ? w[p2] - lse : -1e30f;
        o[3] = v3 ? w[p3] - lse : -1e30f;
        o[4] = v4 ? w[p4] - lse : -1e30f;
        o[5] = v5 ? w[p5] - lse : -1e30f;
        o[6] = v6 ? w[p6] - lse : -1e30f;
    } else {
        int row  = (bid - 9) * 16 + (threadIdx.x >> 5);
        int lane = threadIdx.x & 31;
        const float4* r = (const float4*)(ew + (size_t)row * VV);
        float4 v[16];
#pragma unroll
        for (int i = 0; i < 16; i++) v[i] = r[lane + 32 * i];
        float m = -1e30f;
#pragma unroll
        for (int i = 0; i < 16; i++)
            m = fmaxf(m, fmaxf(fmaxf(v[i].x, v[i].y), fmaxf(v[i].z, v[i].w)));
#pragma unroll
        for (int o = 16; o; o >>= 1) m = fmaxf(m, __shfl_xor_sync(0xffffffffu, m, o));
        float s = 0.f;
#pragma unroll
        for (int i = 0; i < 16; i++)
            s += __expf(v[i].x - m) + __expf(v[i].y - m)
               + __expf(v[i].z - m) + __expf(v[i].w - m);
#pragma unroll
        for (int o = 16; o; o >>= 1) s += __shfl_xor_sync(0xffffffffu, s, o);
        if (lane == 0) g_lse[row] = m + __logf(s);
    }
}

// ---------------------------------------------------------------------------
// K2: smoothed emissions, stored TRANSPOSED (SMT[v][s]). (unchanged, proven)
// ---------------------------------------------------------------------------
__global__ __launch_bounds__(512) void k_smt(const float* __restrict__ ew) {
    extern __shared__ float P[];          // 256*67 floats = 68608 B
    __shared__ float slse[256];
    int tx = threadIdx.x & 31;
    int ty = threadIdx.x >> 5;            // 0..15
    int v0 = blockIdx.x * 64;
    int sbase = blockIdx.y * 256;         // z-plane

    if (threadIdx.x < 256) slse[threadIdx.x] = g_lse[sbase + threadIdx.x];
    __syncthreads();

#pragma unroll
    for (int i = 0; i < 16; i++) {
        int sl = ty + 16 * i;
        float l = slse[sl];
        const float* row = ew + (size_t)(sbase + sl) * VV + v0;
        P[sl * 67 + tx]      = __expf(row[tx]      - l);
        P[sl * 67 + 32 + tx] = __expf(row[32 + tx] - l);
    }
    __syncthreads();

#pragma unroll
    for (int jb = 0; jb < 8; jb++) {
        int sl = jb * 32 + tx;
        int x = sl & 15, y = sl >> 4;
        int sxp = sl + (x < 15);
        int sxm = sl - (x > 0);
        int syp = sl + ((y < 15) ? 16 : 0);
        int sym = sl - ((y > 0)  ? 16 : 0);
#pragma unroll
        for (int k = 0; k < 4; k++) {
            int vl = ty + 16 * k;          // 0..63
            float q = P[sl * 67 + vl] + P[sxp * 67 + vl] + P[sxm * 67 + vl]
                    + P[syp * 67 + vl] + P[sym * 67 + vl];
            g_smt[(size_t)(v0 + vl) * SS + sbase + sl] = __logf(q * 0.2f);
        }
    }
}

// ---------------------------------------------------------------------------
// K3: all_emis, float4-vectorized (4 states/thread)
// ---------------------------------------------------------------------------
__global__ void k_emis(const int* __restrict__ stories) {
    __shared__ int tk[WW];
    int s4 = blockIdx.x * 256 + threadIdx.x;   // float4 index (0..1023)
    int lb = blockIdx.y;                       // lb = l*8 + b
    int l = lb >> 3, b = lb & 7;
    if (threadIdx.x < WW) tk[threadIdx.x] = stories[(b * LL + l) * WW + threadIdx.x];
    __syncthreads();
    float4 acc = make_float4(0.f, 0.f, 0.f, 0.f);
#pragma unroll
    for (int w = 0; w < WW; w++) {
        int t = tk[w];
        if (t < VV) {
            float4 v = ((const float4*)(g_smt + (size_t)t * SS))[s4];
            acc.x += v.x; acc.y += v.y; acc.z += v.z; acc.w += v.w;
        }
    }
    ((float4*)g_emis)[(size_t)lb * (SS / 4) + s4] = acc;
}

// ---------------------------------------------------------------------------
// K4: forward recurrence on 2-CTA clusters, WAIT-FREE-PRODUCER halo push.
// rank0 owns z=0..7, rank1 owns z=8..15 (data flows rank1 -> rank0 only).
// Full-depth halo ring (one slot per step, written once -> no reuse, no
// credits, rank1 NEVER blocks => deadlock structurally impossible).
// rank1 pushes planes 8,9 + 4 boundary cw values into rank0's halo slot l
// (st.shared::cluster), then tid0 publishes a monotonic seq counter in
// rank0's smem. rank0's halo-consumer warps (12..15 only) poll seq >= l
// (volatile LDS, fast path since rank1 runs ahead), acquire-fence, and read
// the halo locally.
// ---------------------------------------------------------------------------
__global__ __launch_bounds__(512, 1) __cluster_dims__(2, 1, 1)
void k_fwd(float* __restrict__ out) {
    // dynamic smem: pbuf[2][HS] then halo[32][HSTRIDE]
    extern __shared__ float dyn[];
    float* pbufs = dyn;                 // 2*HS floats
    float* halo  = dyn + 2 * HS;        // 32*HSTRIDE floats (slot 0 unused)
    __shared__ float cbuf[2][16];
    __shared__ unsigned seq_data;       // meaningful on rank0

    int tid = threadIdx.x;
    int wid = tid >> 5, lane = tid & 31;
    unsigned rank;
    asm("mov.u32 %0, %%cluster_ctarank;" : "=r"(rank));
    unsigned peer = rank ^ 1u;
    int b   = blockIdx.x >> 1;
    int j0l = tid * 4;                 // local state (0..2044)
    int jg  = (int)rank * HS + j0l;    // global state
    int x0 = jg & 15;
    int y  = (jg >> 4) & 15;

    if (tid == 0) seq_data = 0;
    asm volatile("barrier.cluster.arrive.aligned;" ::: "memory");
    asm volatile("barrier.cluster.wait.aligned;" ::: "memory");

    unsigned seq_l  = smem_u32(&seq_data);
    unsigned seq_r  = mapa_peer(seq_l, peer);            // rank1 -> rank0's seq
    unsigned halo_r = mapa_peer(smem_u32(halo), peer);   // rank1 -> rank0's halo

    // Per-state amax + renormalized transition probs (once).
    float Pk[4][7], am[4];
#pragma unroll
    for (int e = 0; e < 4; e++) {
        const float* lp = g_logp + (jg + e) * 7;
        float l[7];
#pragma unroll
        for (int k = 0; k < 7; k++) l[k] = lp[k];
        float m = l[0];
#pragma unroll
        for (int k = 1; k < 7; k++) m = fmaxf(m, l[k]);
        am[e] = m;
#pragma unroll
        for (int k = 0; k < 7; k++) Pk[e][k] = __expf(l[k] - m);  // invalid -> 0
    }

    int wyp = min(wid + 1, 15);
    int wym = max(wid - 1, 0);
    bool edge_hi = (lane >= 28);   // top y-row of this warp's half-plane
    bool edge_lo = (lane < 4);     // bottom y-row

    // l = 0: score0 = emis[0,b,:] + prior
    float4 emv = *(const float4*)(g_emis + (size_t)b * SS + jg);
    float4 prv = *(const float4*)(g_prior + jg);
    float sc[4];
    sc[0] = emv.x + prv.x; sc[1] = emv.y + prv.y;
    sc[2] = emv.z + prv.z; sc[3] = emv.w + prv.w;
    *(float4*)(out + (size_t)b * SS + jg) = make_float4(sc[0], sc[1], sc[2], sc[3]);

    float lm = fmaxf(fmaxf(sc[0], sc[1]), fmaxf(sc[2], sc[3]));
    float cw = key2f(__reduce_max_sync(0xffffffffu, f2key(lm)));

    // prefetch emission for l = 1
    float4 emn = *(const float4*)(g_emis + (size_t)(BB + b) * SS + jg);

    int buf = 0;
    for (int l = 1; l < LL; l++) {
        // publish p~ = exp(sc - c_w) and c_w locally
        float4 p;
        p.x = __expf(sc[0] - cw); p.y = __expf(sc[1] - cw);
        p.z = __expf(sc[2] - cw); p.w = __expf(sc[3] - cw);
        float* pb = pbufs + buf * HS;
        *(float4*)(pb + j0l) = p;
        if (lane == 0) cbuf[buf][wid] = cw;

        // rank1: push halo for step l (planes 8,9 = local j0l<512) + cw of
        // warps 0..3; release-fence per pushing thread. Never blocks.
        if (rank == 1 && tid < 128) {
            unsigned base = halo_r + (unsigned)(l * HSTRIDE) * 4u;
            dsmem_st4(base + (unsigned)j0l * 4u, p);
            if (lane == 0)  // wid 0..3
                dsmem_stf(base + (unsigned)(512 + wid) * 4u, cw);
            asm volatile("fence.acq_rel.cluster;" ::: "memory");
        }

        float emr[4] = {emn.x + am[0], emn.y + am[1], emn.z + am[2], emn.w + am[3]};
        if (l + 1 < LL)
            emn = *(const float4*)(g_emis + (size_t)((l + 1) * BB + b) * SS + jg);

        __syncthreads();   // own pbuf/cbuf complete; pushes done
        if (rank == 1 && tid == 0) {
            asm volatile("fence.acq_rel.cluster;" ::: "memory");
            dsmem_stu(seq_r, (unsigned)l);     // halo slot l ready
        }

        // rank0 halo consumers: wait for slot l (fast path: rank1 runs ahead)
        if (rank == 0 && wid >= 12) {
            seq_wait(seq_l, (unsigned)l);
            asm volatile("fence.acq_rel.cluster;" ::: "memory");
        }

        // cross-warp rescale factors
        float ysel = edge_lo ? cbuf[buf][wym] : (edge_hi ? cbuf[buf][wyp] : cw);
        float s_y  = __expf(ysel - cw);
        const float* hslot = halo + l * HSTRIDE;
        float czp, czq;
        int wzp = wid + 2, wzq = wid + 4;
        if (wzp < 16)        czp = cbuf[buf][wzp];
        else if (rank == 0)  czp = hslot[512 + (wzp - 16)];
        else                 czp = cw;   // global z >= 16: Pk==0 kills it
        if (wzq < 16)        czq = cbuf[buf][wzq];
        else if (rank == 0)  czq = hslot[512 + (wzq - 16)];
        else                 czq = cw;
        float s_zp = __expf(czp - cw);
        float s_zq = __expf(czq - cw);

        float cm1 = (x0 > 0)  ? pb[j0l - 1] : p.x;
        float cp4 = (x0 < 12) ? pb[j0l + 4] : p.w;
        float4 yp = (y < 15) ? *(const float4*)(pb + j0l + 16) : p;
        float4 ym = (y > 0)  ? *(const float4*)(pb + j0l - 16) : p;

        int izp = j0l + 256, izq = j0l + 512;
        float4 zp, zq;
        if (izp < HS)        zp = *(const float4*)(pb + izp);
        else if (rank == 0)  zp = *(const float4*)(hslot + (izp - HS));
        else                 zp = p;     // global z+1 >= 16: Pk==0
        if (izq < HS)        zq = *(const float4*)(pb + izq);
        else if (rank == 0)  zq = *(const float4*)(hslot + (izq - HS));
        else                 zq = p;     // global z+2 >= 16: Pk==0

        float syp_f = edge_hi ? s_y : 1.f;
        float sym_f = edge_lo ? s_y : 1.f;
        yp.x *= syp_f; yp.y *= syp_f; yp.z *= syp_f; yp.w *= syp_f;
        ym.x *= sym_f; ym.y *= sym_f; ym.z *= sym_f; ym.w *= sym_f;
        zp.x *= s_zp;  zp.y *= s_zp;  zp.z *= s_zp;  zp.w *= s_zp;
        zq.x *= s_zq;  zq.y *= s_zq;  zq.z *= s_zq;  zq.w *= s_zq;

        float pc[4]  = {p.x, p.y, p.z, p.w};
        float pxp[4] = {p.y, p.z, p.w, cp4};
        float pxm[4] = {cm1, p.x, p.y, p.z};
        float pyp[4] = {yp.x, yp.y, yp.z, yp.w};
        float pym[4] = {ym.x, ym.y, ym.z, ym.w};
        float pzp[4] = {zp.x, zp.y, zp.z, zp.w};
        float pzq[4] = {zq.x, zq.y, zq.z, zq.w};

        float lmn = -1e30f;
#pragma unroll
        for (int e = 0; e < 4; e++) {
            float q = pc[e]  * Pk[e][0];
            q = fmaf(pxp[e], Pk[e][1], q);
            q = fmaf(pxm[e], Pk[e][2], q);
            q = fmaf(pyp[e], Pk[e][3], q);
            q = fmaf(pym[e], Pk[e][4], q);
            q = fmaf(pzp[e], Pk[e][5], q);
            q = fmaf(pzq[e], Pk[e][6], q);
            sc[e] = emr[e] + __logf(q) + cw;
            lmn = fmaxf(lmn, sc[e]);
        }
        *(float4*)(out + (size_t)(l * BB + b) * SS + jg) =
            make_float4(sc[0], sc[1], sc[2], sc[3]);

        cw = key2f(__reduce_max_sync(0xffffffffu, f2key(lmn)));
        buf ^= 1;
    }

    // keep SMEM alive until the peer's remote writes/reads are done
    asm volatile("barrier.cluster.arrive.aligned;" ::: "memory");
    asm volatile("barrier.cluster.wait.aligned;" ::: "memory");
}

// ---------------------------------------------------------------------------
extern "C" void kernel_launch(void* const* d_in, const int* in_sizes, int n_in,
                              void* d_out, int out_size) {
    const int*   stories = nullptr;
    const float* trans_w = nullptr;
    const float* emis_w  = nullptr;
    const float* prior_w = nullptr;
    for (int i = 0; i < n_in; i++) {
        switch (in_sizes[i]) {
            case 2048:            stories = (const int*)d_in[i];   break;
            case 28672:           trans_w = (const float*)d_in[i]; break;
            case SS * VV:         emis_w  = (const float*)d_in[i]; break;
            case SS:              prior_w = (const float*)d_in[i]; break;
            default: break;
        }
    }
    float* out = (float*)d_out;

    const int smt_smem = 256 * 67 * sizeof(float);               // 68608 B
    const int fwd_smem = (2 * HS + 32 * HSTRIDE) * sizeof(float); // 82944 B
    cudaFuncSetAttribute(k_smt, cudaFuncAttributeMaxDynamicSharedMemorySize, smt_smem);
    cudaFuncSetAttribute(k_fwd, cudaFuncAttributeMaxDynamicSharedMemorySize, fwd_smem);

    k_pre<<<265, 512>>>(prior_w, trans_w, emis_w);
    k_smt<<<dim3(VV / 64, ZP), 512, smt_smem>>>(emis_w);
    k_emis<<<dim3(SS / 1024, LL * BB), 256>>>(stories);
    k_fwd<<<BB * 2, 512, fwd_smem>>>(out);
    (void)out_size;
}

// round 16
// speedup vs baseline: 1.5622x; 1.3095x over previous
#include <cuda_runtime.h>
#include <math.h>

#define SS 4096
#define VV 2048
#define BB 8
#define LL 32
#define WW 8
#define ZP 16
#define HS 2048      // states per CTA in the 2-CTA-cluster forward kernel
#define HSTRIDE 520  // halo slot stride floats (512 plane + 4 cw + pad) = 2080 B
#define HBYTES 2080  // bulk-copy size per slot

// Scratch (no allocation allowed in kernel_launch)
__device__ float g_lse[SS];
__device__ float g_prior[SS];
__device__ float g_logp[SS * 7];
__device__ float g_smt[(size_t)VV * SS];   // transposed smoothed emissions: [v][s]
__device__ float g_emis[LL * BB * SS];     // all_emis, layout (l, b, s)

// Order-preserving float <-> uint key (for REDUX.UMAX warp reduction)
__device__ __forceinline__ unsigned f2key(float f) {
    unsigned u = __float_as_uint(f);
    return u ^ (unsigned)(((int)u >> 31) | 0x80000000);
}
__device__ __forceinline__ float key2f(unsigned k) {
    unsigned u = (k & 0x80000000u) ? (k ^ 0x80000000u) : ~k;
    return __uint_as_float(u);
}

__device__ __forceinline__ unsigned smem_u32(const void* p) {
    return (unsigned)__cvta_generic_to_shared(p);
}
__device__ __forceinline__ unsigned mapa_peer(unsigned laddr, unsigned rank) {
    unsigned r;
    asm("mapa.shared::cluster.u32 %0, %1, %2;" : "=r"(r) : "r"(laddr), "r"(rank));
    return r;
}
// One-shot mbarrier wait, parity 0 (HW-sleep try_wait loop)
__device__ __forceinline__ void mbar_wait0(unsigned mb) {
    unsigned done = 0;
    while (!done) {
        asm volatile(
            "{\n\t.reg .pred p;\n\t"
            "mbarrier.try_wait.parity.acquire.cta.shared::cta.b64 p, [%1], 0, 0x989680;\n\t"
            "selp.b32 %0, 1, 0, p;\n\t}"
            : "=r"(done) : "r"(mb) : "memory");
    }
}

// ---------------------------------------------------------------------------
// K_pre fused (512 threads/block):
//   block 0        : prior log_softmax (8 elems/thread)
//   blocks 1..8    : transition logp (512 states/block)
//   blocks 9..264  : row-lse of emis_w (16 warps -> 16 rows/block, 256 blocks)
// ---------------------------------------------------------------------------
__global__ __launch_bounds__(512) void k_pre(const float* __restrict__ pw,
                                             const float* __restrict__ tw,
                                             const float* __restrict__ ew) {
    int bid = blockIdx.x;
    if (bid == 0) {
        __shared__ float red[16];
        __shared__ float bval;
        int tid = threadIdx.x;
        float v[8];
#pragma unroll
        for (int i = 0; i < 8; i++) v[i] = pw[tid + i * 512];
        float m = v[0];
#pragma unroll
        for (int i = 1; i < 8; i++) m = fmaxf(m, v[i]);
#pragma unroll
        for (int o = 16; o; o >>= 1) m = fmaxf(m, __shfl_xor_sync(0xffffffffu, m, o));
        if ((tid & 31) == 0) red[tid >> 5] = m;
        __syncthreads();
        if (tid < 16) {
            float t = red[tid];
#pragma unroll
            for (int o = 8; o; o >>= 1) t = fmaxf(t, __shfl_xor_sync(0xffffu, t, o));
            if (tid == 0) bval = t;
        }
        __syncthreads();
        m = bval;
        float s = 0.f;
#pragma unroll
        for (int i = 0; i < 8; i++) s += __expf(v[i] - m);
#pragma unroll
        for (int o = 16; o; o >>= 1) s += __shfl_xor_sync(0xffffffffu, s, o);
        if ((tid & 31) == 0) red[tid >> 5] = s;
        __syncthreads();
        if (tid < 16) {
            float t = red[tid];
#pragma unroll
            for (int o = 8; o; o >>= 1) t += __shfl_xor_sync(0xffffu, t, o);
            if (tid == 0) bval = t;
        }
        __syncthreads();
        float lse = m + __logf(bval);
#pragma unroll
        for (int i = 0; i < 8; i++) g_prior[tid + i * 512] = v[i] - lse;
    } else if (bid <= 8) {
        int j = (bid - 1) * 512 + threadIdx.x;
        int x = j & 15, y = (j >> 4) & 15, z = j >> 8;
        int v1 = (x < 15), v2 = (x > 0), v3 = (y < 15), v4 = (y > 0), v5 = (z < 15), v6 = (z < 14);
        int nv = 1 + v1 + v2 + v3 + v4 + v5 + v6;
        float w[7];
#pragma unroll
        for (int k = 0; k < 7; k++) w[k] = tw[j * 7 + k];
        float m = w[0];
#pragma unroll
        for (int k = 1; k < 7; k++) if (k < nv) m = fmaxf(m, w[k]);
        float s = 0.f;
#pragma unroll
        for (int k = 0; k < 7; k++) if (k < nv) s += __expf(w[k] - m);
        float lse = m + __logf(s);
        int p2 = 1 + v1;
        int p3 = p2 + v2;
        int p4 = p3 + v3;
        int p5 = p4 + v4;
        int p6 = p5 + v5;
        float* o = g_logp + j * 7;
        o[0] = w[0] - lse;
        o[1] = v1 ? w[1]  - lse : -1e30f;
        o[2] = v2 ? w[p2] - lse : -1e30f;
        o[3] = v3 ? w[p3] - lse : -1e30f;
        o[4] = v4 ? w[p4] - lse : -1e30f;
        o[5] = v5 ? w[p5] - lse : -1e30f;
        o[6] = v6 ? w[p6] - lse : -1e30f;
    } else {
        int row  = (bid - 9) * 16 + (threadIdx.x >> 5);
        int lane = threadIdx.x & 31;
        const float4* r = (const float4*)(ew + (size_t)row * VV);
        float4 v[16];
#pragma unroll
        for (int i = 0; i < 16; i++) v[i] = r[lane + 32 * i];
        float m = -1e30f;
#pragma unroll
        for (int i = 0; i < 16; i++)
            m = fmaxf(m, fmaxf(fmaxf(v[i].x, v[i].y), fmaxf(v[i].z, v[i].w)));
#pragma unroll
        for (int o = 16; o; o >>= 1) m = fmaxf(m, __shfl_xor_sync(0xffffffffu, m, o));
        float s = 0.f;
#pragma unroll
        for (int i = 0; i < 16; i++)
            s += __expf(v[i].x - m) + __expf(v[i].y - m)
               + __expf(v[i].z - m) + __expf(v[i].w - m);
#pragma unroll
        for (int o = 16; o; o >>= 1) s += __shfl_xor_sync(0xffffffffu, s, o);
        if (lane == 0) g_lse[row] = m + __logf(s);
    }
}

// ---------------------------------------------------------------------------
// K2: smoothed emissions, stored TRANSPOSED (SMT[v][s]). (unchanged, proven)
// ---------------------------------------------------------------------------
__global__ __launch_bounds__(512) void k_smt(const float* __restrict__ ew) {
    extern __shared__ float P[];          // 256*67 floats = 68608 B
    __shared__ float slse[256];
    int tx = threadIdx.x & 31;
    int ty = threadIdx.x >> 5;            // 0..15
    int v0 = blockIdx.x * 64;
    int sbase = blockIdx.y * 256;         // z-plane

    if (threadIdx.x < 256) slse[threadIdx.x] = g_lse[sbase + threadIdx.x];
    __syncthreads();

#pragma unroll
    for (int i = 0; i < 16; i++) {
        int sl = ty + 16 * i;
        float l = slse[sl];
        const float* row = ew + (size_t)(sbase + sl) * VV + v0;
        P[sl * 67 + tx]      = __expf(row[tx]      - l);
        P[sl * 67 + 32 + tx] = __expf(row[32 + tx] - l);
    }
    __syncthreads();

#pragma unroll
    for (int jb = 0; jb < 8; jb++) {
        int sl = jb * 32 + tx;
        int x = sl & 15, y = sl >> 4;
        int sxp = sl + (x < 15);
        int sxm = sl - (x > 0);
        int syp = sl + ((y < 15) ? 16 : 0);
        int sym = sl - ((y > 0)  ? 16 : 0);
#pragma unroll
        for (int k = 0; k < 4; k++) {
            int vl = ty + 16 * k;          // 0..63
            float q = P[sl * 67 + vl] + P[sxp * 67 + vl] + P[sxm * 67 + vl]
                    + P[syp * 67 + vl] + P[sym * 67 + vl];
            g_smt[(size_t)(v0 + vl) * SS + sbase + sl] = __logf(q * 0.2f);
        }
    }
}

// ---------------------------------------------------------------------------
// K3: all_emis, float4-vectorized (4 states/thread)
// ---------------------------------------------------------------------------
__global__ void k_emis(const int* __restrict__ stories) {
    __shared__ int tk[WW];
    int s4 = blockIdx.x * 256 + threadIdx.x;   // float4 index (0..1023)
    int lb = blockIdx.y;                       // lb = l*8 + b
    int l = lb >> 3, b = lb & 7;
    if (threadIdx.x < WW) tk[threadIdx.x] = stories[(b * LL + l) * WW + threadIdx.x];
    __syncthreads();
    float4 acc = make_float4(0.f, 0.f, 0.f, 0.f);
#pragma unroll
    for (int w = 0; w < WW; w++) {
        int t = tk[w];
        if (t < VV) {
            float4 v = ((const float4*)(g_smt + (size_t)t * SS))[s4];
            acc.x += v.x; acc.y += v.y; acc.z += v.z; acc.w += v.w;
        }
    }
    ((float4*)g_emis)[(size_t)lb * (SS / 4) + s4] = acc;
}

// ---------------------------------------------------------------------------
// K4: forward recurrence on 2-CTA clusters; halo transfer via ONE
// cp.async.bulk (UBLKCP) per step into a full-depth ring with ONE-SHOT
// mbarriers (init count 1 + arrive.expect_tx(HBYTES) at startup; each flips
// exactly once -> no parity reuse, no credits, producer never waits).
// rank1 stages its halo slice (planes 8,9 + 4 cw) in its OWN halo slot l
// (written once, doubles as copy source -> no WAR), __syncthreads, then one
// elected thread: fence.proxy.async + bulk copy -> rank0's slot l,
// complete_tx on rank0's mb[l]. rank0's halo-consumer warps (12..15) do a
// HW-sleep try_wait (fast path ~90cyc since rank1 runs ahead) and read the
// halo locally. No per-thread cluster fences anywhere.
// ---------------------------------------------------------------------------
__global__ __launch_bounds__(512, 1) __cluster_dims__(2, 1, 1)
void k_fwd(float* __restrict__ out) {
    // dynamic smem: pbuf[2][HS] then halo[32][HSTRIDE]
    extern __shared__ float dyn[];
    float* pbufs = dyn;                 // 2*HS floats
    float* halo  = dyn + 2 * HS;        // 32*HSTRIDE floats (slot 0 unused)
    __shared__ float cbuf[2][16];
    __shared__ __align__(8) unsigned long long mb[LL];   // one-shot barriers (rank0)

    int tid = threadIdx.x;
    int wid = tid >> 5, lane = tid & 31;
    unsigned rank;
    asm("mov.u32 %0, %%cluster_ctarank;" : "=r"(rank));
    unsigned peer = rank ^ 1u;
    int b   = blockIdx.x >> 1;
    int j0l = tid * 4;                 // local state (0..2044)
    int jg  = (int)rank * HS + j0l;    // global state
    int x0 = jg & 15;
    int y  = (jg >> 4) & 15;

    // Init one-shot mbarriers: count 1, then arrive with expect_tx(HBYTES).
    // Phase 0 completes exactly when the peer's HBYTES bulk copy lands.
    if (tid == 0) {
#pragma unroll 1
        for (int l = 1; l < LL; l++) {
            unsigned a = smem_u32(&mb[l]);
            asm volatile("mbarrier.init.shared.b64 [%0], 1;" :: "r"(a) : "memory");
            asm volatile("mbarrier.arrive.expect_tx.shared.b64 _, [%0], %1;"
                         :: "r"(a), "r"((unsigned)HBYTES) : "memory");
        }
    }
    __syncthreads();
    asm volatile("barrier.cluster.arrive.aligned;" ::: "memory");
    asm volatile("barrier.cluster.wait.aligned;" ::: "memory");

    unsigned halo_l = smem_u32(halo);
    unsigned halo_r = mapa_peer(halo_l, peer);               // rank1 -> rank0 halo
    unsigned mb0_r  = mapa_peer(smem_u32(&mb[0]), peer);     // peer mb array base

    // Per-state amax + renormalized transition probs (once).
    float Pk[4][7], am[4];
#pragma unroll
    for (int e = 0; e < 4; e++) {
        const float* lp = g_logp + (jg + e) * 7;
        float l[7];
#pragma unroll
        for (int k = 0; k < 7; k++) l[k] = lp[k];
        float m = l[0];
#pragma unroll
        for (int k = 1; k < 7; k++) m = fmaxf(m, l[k]);
        am[e] = m;
#pragma unroll
        for (int k = 0; k < 7; k++) Pk[e][k] = __expf(l[k] - m);  // invalid -> 0
    }

    int wyp = min(wid + 1, 15);
    int wym = max(wid - 1, 0);
    bool edge_hi = (lane >= 28);   // top y-row of this warp's half-plane
    bool edge_lo = (lane < 4);     // bottom y-row

    // l = 0: score0 = emis[0,b,:] + prior
    float4 emv = *(const float4*)(g_emis + (size_t)b * SS + jg);
    float4 prv = *(const float4*)(g_prior + jg);
    float sc[4];
    sc[0] = emv.x + prv.x; sc[1] = emv.y + prv.y;
    sc[2] = emv.z + prv.z; sc[3] = emv.w + prv.w;
    *(float4*)(out + (size_t)b * SS + jg) = make_float4(sc[0], sc[1], sc[2], sc[3]);

    float lm = fmaxf(fmaxf(sc[0], sc[1]), fmaxf(sc[2], sc[3]));
    float cw = key2f(__reduce_max_sync(0xffffffffu, f2key(lm)));

    // prefetch emission for l = 1
    float4 emn = *(const float4*)(g_emis + (size_t)(BB + b) * SS + jg);

    int buf = 0;
    for (int l = 1; l < LL; l++) {
        // publish p~ = exp(sc - c_w) and c_w locally
        float4 p;
        p.x = __expf(sc[0] - cw); p.y = __expf(sc[1] - cw);
        p.z = __expf(sc[2] - cw); p.w = __expf(sc[3] - cw);
        float* pb = pbufs + buf * HS;
        *(float4*)(pb + j0l) = p;
        if (lane == 0) cbuf[buf][wid] = cw;

        // rank1: stage halo slice in OWN halo slot l (planes 8,9 + cw[0..3])
        float* hstage = halo + l * HSTRIDE;
        if (rank == 1 && tid < 128) {
            *(float4*)(hstage + j0l) = p;
            if (lane == 0) hstage[512 + wid] = cw;   // wid 0..3
        }

        float emr[4] = {emn.x + am[0], emn.y + am[1], emn.z + am[2], emn.w + am[3]};
        if (l + 1 < LL)
            emn = *(const float4*)(g_emis + (size_t)((l + 1) * BB + b) * SS + jg);

        __syncthreads();   // own pbuf/cbuf/staging complete

        // rank1: single bulk async copy staging -> rank0's slot l, completing
        // on rank0's one-shot mb[l]. Producer NEVER waits.
        if (rank == 1 && tid == 0) {
            asm volatile("fence.proxy.async.shared::cta;" ::: "memory");
            unsigned dst = halo_r + (unsigned)(l * HSTRIDE) * 4u;
            unsigned src = halo_l + (unsigned)(l * HSTRIDE) * 4u;
            unsigned mbr = mb0_r + (unsigned)l * 8u;
            asm volatile(
                "cp.async.bulk.shared::cluster.shared::cta.mbarrier::complete_tx::bytes "
                "[%0], [%1], %2, [%3];"
                :: "r"(dst), "r"(src), "r"((unsigned)HBYTES), "r"(mbr) : "memory");
        }

        // rank0 halo consumers: one-shot wait (fast path: rank1 runs ahead)
        if (rank == 0 && wid >= 12) {
            mbar_wait0(smem_u32(&mb[l]));
        }

        // cross-warp rescale factors
        float ysel = edge_lo ? cbuf[buf][wym] : (edge_hi ? cbuf[buf][wyp] : cw);
        float s_y  = __expf(ysel - cw);
        const float* hslot = halo + l * HSTRIDE;
        float czp, czq;
        int wzp = wid + 2, wzq = wid + 4;
        if (wzp < 16)        czp = cbuf[buf][wzp];
        else if (rank == 0)  czp = hslot[512 + (wzp - 16)];
        else                 czp = cw;   // global z >= 16: Pk==0 kills it
        if (wzq < 16)        czq = cbuf[buf][wzq];
        else if (rank == 0)  czq = hslot[512 + (wzq - 16)];
        else                 czq = cw;
        float s_zp = __expf(czp - cw);
        float s_zq = __expf(czq - cw);

        float cm1 = (x0 > 0)  ? pb[j0l - 1] : p.x;
        float cp4 = (x0 < 12) ? pb[j0l + 4] : p.w;
        float4 yp = (y < 15) ? *(const float4*)(pb + j0l + 16) : p;
        float4 ym = (y > 0)  ? *(const float4*)(pb + j0l - 16) : p;

        int izp = j0l + 256, izq = j0l + 512;
        float4 zp, zq;
        if (izp < HS)        zp = *(const float4*)(pb + izp);
        else if (rank == 0)  zp = *(const float4*)(hslot + (izp - HS));
        else                 zp = p;     // global z+1 >= 16: Pk==0
        if (izq < HS)        zq = *(const float4*)(pb + izq);
        else if (rank == 0)  zq = *(const float4*)(hslot + (izq - HS));
        else                 zq = p;     // global z+2 >= 16: Pk==0

        float syp_f = edge_hi ? s_y : 1.f;
        float sym_f = edge_lo ? s_y : 1.f;
        yp.x *= syp_f; yp.y *= syp_f; yp.z *= syp_f; yp.w *= syp_f;
        ym.x *= sym_f; ym.y *= sym_f; ym.z *= sym_f; ym.w *= sym_f;
        zp.x *= s_zp;  zp.y *= s_zp;  zp.z *= s_zp;  zp.w *= s_zp;
        zq.x *= s_zq;  zq.y *= s_zq;  zq.z *= s_zq;  zq.w *= s_zq;

        float pc[4]  = {p.x, p.y, p.z, p.w};
        float pxp[4] = {p.y, p.z, p.w, cp4};
        float pxm[4] = {cm1, p.x, p.y, p.z};
        float pyp[4] = {yp.x, yp.y, yp.z, yp.w};
        float pym[4] = {ym.x, ym.y, ym.z, ym.w};
        float pzp[4] = {zp.x, zp.y, zp.z, zp.w};
        float pzq[4] = {zq.x, zq.y, zq.z, zq.w};

        float lmn = -1e30f;
#pragma unroll
        for (int e = 0; e < 4; e++) {
            float q = pc[e]  * Pk[e][0];
            q = fmaf(pxp[e], Pk[e][1], q);
            q = fmaf(pxm[e], Pk[e][2], q);
            q = fmaf(pyp[e], Pk[e][3], q);
            q = fmaf(pym[e], Pk[e][4], q);
            q = fmaf(pzp[e], Pk[e][5], q);
            q = fmaf(pzq[e], Pk[e][6], q);
            sc[e] = emr[e] + __logf(q) + cw;
            lmn = fmaxf(lmn, sc[e]);
        }
        *(float4*)(out + (size_t)(l * BB + b) * SS + jg) =
            make_float4(sc[0], sc[1], sc[2], sc[3]);

        cw = key2f(__reduce_max_sync(0xffffffffu, f2key(lmn)));
        buf ^= 1;
    }

    // keep SMEM alive until the peer's remote copies/reads are done
    asm volatile("barrier.cluster.arrive.aligned;" ::: "memory");
    asm volatile("barrier.cluster.wait.aligned;" ::: "memory");
}

// ---------------------------------------------------------------------------
extern "C" void kernel_launch(void* const* d_in, const int* in_sizes, int n_in,
                              void* d_out, int out_size) {
    const int*   stories = nullptr;
    const float* trans_w = nullptr;
    const float* emis_w  = nullptr;
    const float* prior_w = nullptr;
    for (int i = 0; i < n_in; i++) {
        switch (in_sizes[i]) {
            case 2048:            stories = (const int*)d_in[i];   break;
            case 28672:           trans_w = (const float*)d_in[i]; break;
            case SS * VV:         emis_w  = (const float*)d_in[i]; break;
            case SS:              prior_w = (const float*)d_in[i]; break;
            default: break;
        }
    }
    float* out = (float*)d_out;

    const int smt_smem = 256 * 67 * sizeof(float);                // 68608 B
    const int fwd_smem = (2 * HS + 32 * HSTRIDE) * sizeof(float); // 82944 B
    cudaFuncSetAttribute(k_smt, cudaFuncAttributeMaxDynamicSharedMemorySize, smt_smem);
    cudaFuncSetAttribute(k_fwd, cudaFuncAttributeMaxDynamicSharedMemorySize, fwd_smem);

    k_pre<<<265, 512>>>(prior_w, trans_w, emis_w);
    k_smt<<<dim3(VV / 64, ZP), 512, smt_smem>>>(emis_w);
    k_emis<<<dim3(SS / 1024, LL * BB), 256>>>(stories);
    k_fwd<<<BB * 2, 512, fwd_smem>>>(out);
    (void)out_size;
}